// round 8
// baseline (speedup 1.0000x reference)
#include <cuda_runtime.h>
#include <cuda_bf16.h>
#include <cstdint>
#include <cstddef>

#define NB 32
#define NN 1024
#define NF 64
#define NO 128

typedef unsigned long long u64;
typedef uint32_t u32;

// Precomputed A as bf16 hi/lo in B-operand layout [n][k] (n=0..255, k=0..63)
__device__ __align__(16) __nv_bfloat16 Bhi_g[256 * 64];
__device__ __align__(16) __nv_bfloat16 Blo_g[256 * 64];

// ---------------------------------------------------------------------------
// smem layout (bytes). X/B tiles use padded 144B rows (128B data + 16B pad)
// so ldmatrix 8-row accesses are bank-conflict-free without swizzle.
// ---------------------------------------------------------------------------
#define OFF_COORD 0                          // float4 (x, y, K*r, 0) [1024] = 16KB
#define OFF_COEF  16384                      // c1s[128], c2s[128], ms[128]
#define OFF_RED   17920                      // redw[512], redd[512]
#define OFF_A2    22016                      // A2s[128]
#define OFF_BS    22528                      // bs[128]
#define OFF_XHI   23040                      // 128 rows x 144B
#define OFF_XLO   (OFF_XHI + 128 * 144)
#define OFF_BHI   (OFF_XLO + 128 * 144)      // 256 rows x 144B
#define OFF_BLO   (OFF_BHI + 256 * 144)
#define SMEM_TOTAL (OFF_BLO + 256 * 144)     // 133632 B

#define KC (-14.4269504089f)                 // -10 * log2(e)
#define INV_KC (-0.0693147181f)              // 1 / KC

__device__ __forceinline__ u32 smem_u32(const void* p) {
    u32 a;
    asm("{ .reg .u64 t; cvta.to.shared.u64 t, %1; cvt.u32.u64 %0, t; }" : "=r"(a) : "l"(p));
    return a;
}
__device__ __forceinline__ float fast_exp2(float t) {
    float r; asm("ex2.approx.f32 %0, %1;" : "=f"(r) : "f"(t)); return r;
}
#define LDSM_X4(r0, r1, r2, r3, addr) \
    asm volatile("ldmatrix.sync.aligned.m8n8.x4.shared.b16 {%0,%1,%2,%3}, [%4];" \
                 : "=r"(r0), "=r"(r1), "=r"(r2), "=r"(r3) : "r"(addr))

__device__ __forceinline__ void mma16816(float* d, const u32* a, const u32* b) {
    asm volatile(
        "mma.sync.aligned.m16n8k16.row.col.f32.bf16.bf16.f32 "
        "{%0,%1,%2,%3}, {%4,%5,%6,%7}, {%8,%9}, {%0,%1,%2,%3};"
        : "+f"(d[0]), "+f"(d[1]), "+f"(d[2]), "+f"(d[3])
        : "r"(a[0]), "r"(a[1]), "r"(a[2]), "r"(a[3]), "r"(b[0]), "r"(b[1]));
}

// ---------------------------------------------------------------------------
// Prep: convert A -> Bhi/Blo bf16, layout [n][k]
// ---------------------------------------------------------------------------
__global__ void prep_kernel(const float* __restrict__ A) {
    int idx = blockIdx.x * blockDim.x + threadIdx.x;   // 0..16383
    int n = idx >> 6, k = idx & 63;
    float a = (n < 128) ? A[k * 128 + n] : A[(64 + k) * 128 + (n - 128)];
    __nv_bfloat16 h = __float2bfloat16_rn(a);
    float r = a - __bfloat162float(h);
    Bhi_g[idx] = h;
    Blo_g[idx] = __float2bfloat16_rn(r);
}

// ---------------------------------------------------------------------------
// Phase functions (force-inlined; called in both warp orders)
// ---------------------------------------------------------------------------
__device__ __forceinline__ void mma_phase(
    float acc[2][8][4], u32 sbase, int m0, const u32* nbase,
    u32 arow, u32 acol, u32 brow, u32 bcol)
{
    #pragma unroll
    for (int term = 0; term < 3; term++) {
        const u32 Xb = sbase + ((term == 2) ? OFF_XLO : OFF_XHI);
        const u32 Bb = sbase + ((term == 1) ? OFF_BLO : OFF_BHI);
        #pragma unroll
        for (int k = 0; k < 4; k++) {
            u32 af[2][4];
            #pragma unroll
            for (int mt = 0; mt < 2; mt++) {
                u32 addr = Xb + (m0 + mt * 16 + arow) * 144 + k * 32 + acol;
                LDSM_X4(af[mt][0], af[mt][1], af[mt][2], af[mt][3], addr);
            }
            u32 bf[8][2];
            #pragma unroll
            for (int p = 0; p < 4; p++) {
                u32 addr = Bb + (nbase[p] + brow) * 144 + k * 32 + bcol;
                LDSM_X4(bf[2 * p][0], bf[2 * p][1], bf[2 * p + 1][0], bf[2 * p + 1][1], addr);
            }
            #pragma unroll
            for (int nb = 0; nb < 8; nb++) {
                mma16816(acc[0][nb], af[0], bf[nb]);
                mma16816(acc[1][nb], af[1], bf[nb]);
            }
        }
    }
}

// u = K*(ri + rj - 2*ci.cj) = K*d <= 0 always  ->  ex2(u) in (0,1], no overflow.
// ws = sum e;  dw = sum d*e = (1/K) * sum u*e.
__device__ __forceinline__ void pair_phase(
    const float4* coords, float* redw, float* redd, int t, int seg)
{
    const int jloc = t & 127;
    const int quarter = t >> 7;
    const float4 cj = coords[seg * 128 + jloc];
    const float Km2jx = -2.0f * KC * cj.x;
    const float Km2jy = -2.0f * KC * cj.y;
    const float Krj = cj.z;                 // K * |cj|^2

    float S1a = 0.f, S1b = 0.f, S2a = 0.f, S2b = 0.f;
    const int i0 = quarter * 256;
    #pragma unroll 4
    for (int i = i0; i < i0 + 256; i += 2) {
        float4 c0 = coords[i];
        float4 c1 = coords[i + 1];
        float u0 = fmaf(c0.x, Km2jx, fmaf(c0.y, Km2jy, c0.z + Krj));
        float e0 = fast_exp2(u0);
        S1a += e0;
        S2a = fmaf(u0, e0, S2a);
        float u1 = fmaf(c1.x, Km2jx, fmaf(c1.y, Km2jy, c1.z + Krj));
        float e1 = fast_exp2(u1);
        S1b += e1;
        S2b = fmaf(u1, e1, S2b);
    }
    redw[quarter * 128 + jloc] = S1a + S1b;
    redd[quarter * 128 + jloc] = (S2a + S2b) * INV_KC;
}

// ---------------------------------------------------------------------------
// Fused kernel: per CTA, 128 rows of one batch. grid=256, block=512.
// Even warps: MMA then pairwise.  Odd warps: pairwise then MMA.
// ---------------------------------------------------------------------------
__global__ void __launch_bounds__(512, 1) fused_kernel(
    const float* __restrict__ x,
    const float* __restrict__ mask,
    const float* __restrict__ A,
    const float* __restrict__ bias,
    float* __restrict__ out)
{
    extern __shared__ __align__(1024) char sm[];
    const u32 sbase = smem_u32(sm);
    const int t = threadIdx.x;
    const int wid = t >> 5;
    const int lane = t & 31;

    const int b   = blockIdx.x >> 3;
    const int seg = blockIdx.x & 7;
    const int row0 = b * NN + seg * 128;

    float4* coords = (float4*)(sm + OFF_COORD);
    float* c1s = (float*)(sm + OFF_COEF);
    float* c2s = c1s + 128;
    float* ms  = c2s + 128;
    float* redw = (float*)(sm + OFF_RED);
    float* redd = redw + 512;
    float* A2s = (float*)(sm + OFF_A2);
    float* bs  = (float*)(sm + OFF_BS);

    // ---- prologue loads ----
    for (int i = t; i < NN; i += 512) {
        float2 c = *(const float2*)(x + ((size_t)b * NN + i) * NF + (NF - 2));
        float r = fmaf(c.y, c.y, c.x * c.x);
        coords[i] = make_float4(c.x, c.y, KC * r, 0.f);
    }

    // x tile -> bf16 hi/lo into padded smem. thread: row=t>>2, 16 cols
    {
        int row = t >> 2;
        int cb  = (t & 3) * 16;
        const float* xr = x + (size_t)(row0 + row) * NF + cb;
        char* xh = sm + OFF_XHI + row * 144 + cb * 2;
        char* xl = sm + OFF_XLO + row * 144 + cb * 2;
        #pragma unroll
        for (int q = 0; q < 4; q++) {
            float4 v = *(const float4*)(xr + q * 4);
            __nv_bfloat16 h0 = __float2bfloat16_rn(v.x);
            __nv_bfloat16 h1 = __float2bfloat16_rn(v.y);
            __nv_bfloat16 h2 = __float2bfloat16_rn(v.z);
            __nv_bfloat16 h3 = __float2bfloat16_rn(v.w);
            __nv_bfloat16 l0 = __float2bfloat16_rn(v.x - __bfloat162float(h0));
            __nv_bfloat16 l1 = __float2bfloat16_rn(v.y - __bfloat162float(h1));
            __nv_bfloat16 l2 = __float2bfloat16_rn(v.z - __bfloat162float(h2));
            __nv_bfloat16 l3 = __float2bfloat16_rn(v.w - __bfloat162float(h3));
            u32 hi01 = ((u32)__bfloat16_as_ushort(h1) << 16) | __bfloat16_as_ushort(h0);
            u32 hi23 = ((u32)__bfloat16_as_ushort(h3) << 16) | __bfloat16_as_ushort(h2);
            u32 lo01 = ((u32)__bfloat16_as_ushort(l1) << 16) | __bfloat16_as_ushort(l0);
            u32 lo23 = ((u32)__bfloat16_as_ushort(l3) << 16) | __bfloat16_as_ushort(l2);
            *(u32*)(xh + q * 8)     = hi01;
            *(u32*)(xh + q * 8 + 4) = hi23;
            *(u32*)(xl + q * 8)     = lo01;
            *(u32*)(xl + q * 8 + 4) = lo23;
        }
    }

    // B tiles: bf16 globals -> padded smem rows
    {
        const uint4* bh = (const uint4*)Bhi_g;
        const uint4* bl = (const uint4*)Blo_g;
        for (int idx = t; idx < 2048; idx += 512) {        // 256 rows x 8 chunks
            int row = idx >> 3, q = idx & 7;
            char* dst_off = sm + row * 144 + q * 16;
            *(uint4*)(dst_off + OFF_BHI) = bh[idx];
            *(uint4*)(dst_off + OFF_BLO) = bl[idx];
        }
    }

    if (t < 128) {
        A2s[t] = A[128 * 128 + t];
        bs[t]  = bias[t];
    }
    __syncthreads();

    // ---- two phases, order-swapped per warp parity (pipe overlap) ----
    const int m0  = (wid & 3) * 32;     // warp rows
    const int c0w = (wid >> 2) * 32;    // warp G0 col base (G1 = +128)
    const int g = lane >> 3, ri = lane & 7;
    const u32 arow = ri + ((g & 1) << 3);
    const u32 acol = (g >> 1) << 4;
    const u32 brow = ri + ((g >> 1) << 3);
    const u32 bcol = (g & 1) << 4;
    const u32 nbase[4] = { (u32)c0w, (u32)c0w + 16, (u32)c0w + 128, (u32)c0w + 144 };

    float acc[2][8][4];
    #pragma unroll
    for (int mt = 0; mt < 2; mt++)
        #pragma unroll
        for (int nb = 0; nb < 8; nb++)
            #pragma unroll
            for (int e = 0; e < 4; e++)
                acc[mt][nb][e] = 0.f;

    if (wid & 1) {
        pair_phase(coords, redw, redd, t, seg);
        mma_phase(acc, sbase, m0, nbase, arow, acol, brow, bcol);
    } else {
        mma_phase(acc, sbase, m0, nbase, arow, acol, brow, bcol);
        pair_phase(coords, redw, redd, t, seg);
    }
    __syncthreads();

    if (t < 128) {
        float ws = (redw[t] + redw[128 + t]) + (redw[256 + t] + redw[384 + t]);
        float dw = (redd[t] + redd[128 + t]) + (redd[256 + t] + redd[384 + t]);
        float m = mask[row0 + t];
        ms[t]  = m;
        c1s[t] = fmaf(ws, m, -1.0f);
        c2s[t] = dw * m;
    }
    __syncthreads();

    // ---- epilogue ----
    #pragma unroll
    for (int mt = 0; mt < 2; mt++) {
        const int r1 = m0 + mt * 16 + (lane >> 2);
        const int r2 = r1 + 8;
        const float m1 = ms[r1],  mA = ms[r2];
        const float c11 = c1s[r1], c12 = c1s[r2];
        const float c21 = c2s[r1], c22 = c2s[r2];
        #pragma unroll
        for (int nb = 0; nb < 4; nb++) {
            const int col = c0w + nb * 8 + (lane & 3) * 2;
            const float a20 = A2s[col], a21 = A2s[col + 1];
            const float b0 = bs[col],  b1 = bs[col + 1];
            const float* g0 = acc[mt][nb];
            const float* g1 = acc[mt][nb + 4];
            float2 o1, o2;
            o1.x = (fmaf(c11, g1[0], g0[0]) + fmaf(c21, a20, b0)) * m1;
            o1.y = (fmaf(c11, g1[1], g0[1]) + fmaf(c21, a21, b1)) * m1;
            o2.x = (fmaf(c12, g1[2], g0[2]) + fmaf(c22, a20, b0)) * mA;
            o2.y = (fmaf(c12, g1[3], g0[3]) + fmaf(c22, a21, b1)) * mA;
            *(float2*)(out + (size_t)(row0 + r1) * NO + col) = o1;
            *(float2*)(out + (size_t)(row0 + r2) * NO + col) = o2;
        }
    }
}

extern "C" void kernel_launch(void* const* d_in, const int* in_sizes, int n_in,
                              void* d_out, int out_size) {
    const float* x    = (const float*)d_in[0];
    const float* mask = (const float*)d_in[1];
    const float* A    = (const float*)d_in[2];
    const float* bias = (const float*)d_in[3];
    float* out = (float*)d_out;

    cudaFuncSetAttribute(fused_kernel, cudaFuncAttributeMaxDynamicSharedMemorySize, SMEM_TOTAL);

    prep_kernel<<<16, 1024>>>(A);
    fused_kernel<<<NB * 8, 512, SMEM_TOTAL>>>(x, mask, A, bias, out);
}

// round 9
// speedup vs baseline: 1.0626x; 1.0626x over previous
#include <cuda_runtime.h>
#include <cuda_bf16.h>
#include <cstdint>
#include <cstddef>

#define NB 32
#define NN 1024
#define NF 64
#define NO 128

typedef unsigned long long u64;
typedef uint32_t u32;

// Precomputed A as bf16 hi/lo in B-operand layout [n][k] (n=0..255, k=0..63)
__device__ __align__(16) __nv_bfloat16 Bhi_g[256 * 64];
__device__ __align__(16) __nv_bfloat16 Blo_g[256 * 64];

// ---------------------------------------------------------------------------
// smem layout (bytes). X/B tiles use padded 144B rows (128B data + 16B pad)
// so ldmatrix 8-row accesses are bank-conflict-free without swizzle.
// Coords are SoA so packed f32x2 loads need no shuffling.
// ---------------------------------------------------------------------------
#define OFF_CX    0                          // xs[1024] (4KB)
#define OFF_CY    4096                       // ys[1024] (4KB)
#define OFF_CZ    8192                       // kz[1024] = K*|c|^2 (4KB)
#define OFF_COEF  12288                      // c1s[128], c2s[128], ms[128]
#define OFF_RED   13824                      // redw[512], redd[512] (4KB)
#define OFF_A2    17920                      // A2s[128]
#define OFF_BS    18432                      // bs[128]
#define OFF_XHI   19456                      // 128 rows x 144B
#define OFF_XLO   (OFF_XHI + 128 * 144)
#define OFF_BHI   (OFF_XLO + 128 * 144)      // 256 rows x 144B
#define OFF_BLO   (OFF_BHI + 256 * 144)
#define SMEM_TOTAL (OFF_BLO + 256 * 144)     // 130048 B

#define KC (-14.4269504089f)                 // -10 * log2(e)
#define INV_KC (-0.0693147181f)              // 1 / KC

__device__ __forceinline__ u32 smem_u32(const void* p) {
    u32 a;
    asm("{ .reg .u64 t; cvta.to.shared.u64 t, %1; cvt.u32.u64 %0, t; }" : "=r"(a) : "l"(p));
    return a;
}
__device__ __forceinline__ float fast_exp2(float t) {
    float r; asm("ex2.approx.f32 %0, %1;" : "=f"(r) : "f"(t)); return r;
}
__device__ __forceinline__ u64 pk2f(float lo, float hi) {
    u64 r; asm("mov.b64 %0, {%1, %2};" : "=l"(r) : "f"(lo), "f"(hi)); return r;
}
__device__ __forceinline__ void up2f(u64 v, float& a, float& b) {
    asm("mov.b64 {%0, %1}, %2;" : "=f"(a), "=f"(b) : "l"(v));
}
#define ADD2(d, a, b)   asm("add.rn.f32x2 %0, %1, %2;" : "=l"(d) : "l"(a), "l"(b))
#define FMA2IO(d, a, b) asm("fma.rn.f32x2 %0, %1, %2, %0;" : "+l"(d) : "l"(a), "l"(b))
#define ADD2ACC(d, a)   asm("add.rn.f32x2 %0, %1, %0;" : "+l"(d) : "l"(a))

#define LDSM_X4(r0, r1, r2, r3, addr) \
    asm volatile("ldmatrix.sync.aligned.m8n8.x4.shared.b16 {%0,%1,%2,%3}, [%4];" \
                 : "=r"(r0), "=r"(r1), "=r"(r2), "=r"(r3) : "r"(addr))

__device__ __forceinline__ void mma16816(float* d, const u32* a, const u32* b) {
    asm volatile(
        "mma.sync.aligned.m16n8k16.row.col.f32.bf16.bf16.f32 "
        "{%0,%1,%2,%3}, {%4,%5,%6,%7}, {%8,%9}, {%0,%1,%2,%3};"
        : "+f"(d[0]), "+f"(d[1]), "+f"(d[2]), "+f"(d[3])
        : "r"(a[0]), "r"(a[1]), "r"(a[2]), "r"(a[3]), "r"(b[0]), "r"(b[1]));
}

// ---------------------------------------------------------------------------
// Prep: convert A -> Bhi/Blo bf16, layout [n][k]
// ---------------------------------------------------------------------------
__global__ void prep_kernel(const float* __restrict__ A) {
    int idx = blockIdx.x * blockDim.x + threadIdx.x;   // 0..16383
    int n = idx >> 6, k = idx & 63;
    float a = (n < 128) ? A[k * 128 + n] : A[(64 + k) * 128 + (n - 128)];
    __nv_bfloat16 h = __float2bfloat16_rn(a);
    float r = a - __bfloat162float(h);
    Bhi_g[idx] = h;
    Blo_g[idx] = __float2bfloat16_rn(r);
}

// ---------------------------------------------------------------------------
// MMA phase: 3-term bf16 split (xhi*Bhi + xhi*Blo + xlo*Bhi)
// ---------------------------------------------------------------------------
__device__ __forceinline__ void mma_phase(
    float acc[2][8][4], u32 sbase, int m0, const u32* nbase,
    u32 arow, u32 acol, u32 brow, u32 bcol)
{
    #pragma unroll
    for (int mt = 0; mt < 2; mt++)
        #pragma unroll
        for (int nb = 0; nb < 8; nb++)
            #pragma unroll
            for (int e = 0; e < 4; e++)
                acc[mt][nb][e] = 0.f;

    #pragma unroll
    for (int term = 0; term < 3; term++) {
        const u32 Xb = sbase + ((term == 2) ? OFF_XLO : OFF_XHI);
        const u32 Bb = sbase + ((term == 1) ? OFF_BLO : OFF_BHI);
        #pragma unroll
        for (int k = 0; k < 4; k++) {
            u32 af[2][4];
            #pragma unroll
            for (int mt = 0; mt < 2; mt++) {
                u32 addr = Xb + (m0 + mt * 16 + arow) * 144 + k * 32 + acol;
                LDSM_X4(af[mt][0], af[mt][1], af[mt][2], af[mt][3], addr);
            }
            u32 bf[8][2];
            #pragma unroll
            for (int p = 0; p < 4; p++) {
                u32 addr = Bb + (nbase[p] + brow) * 144 + k * 32 + bcol;
                LDSM_X4(bf[2 * p][0], bf[2 * p][1], bf[2 * p + 1][0], bf[2 * p + 1][1], addr);
            }
            #pragma unroll
            for (int nb = 0; nb < 8; nb++) {
                mma16816(acc[0][nb], af[0], bf[nb]);
                mma16816(acc[1][nb], af[1], bf[nb]);
            }
        }
    }
}

// ---------------------------------------------------------------------------
// Pairwise phase, f32x2-packed over SoA coords.
// u = K*(ri + rj - 2*ci.cj) = K*d <= 0 -> ex2(u) in (0,1], overflow-safe.
// ws = sum e;  dw = (1/K) * sum u*e.
// Per 4 points: 3 LDS.128 + 10 wide fma-ops + 4 EX2.
// ---------------------------------------------------------------------------
__device__ __forceinline__ void pair_phase(
    const char* sm, float* redw, float* redd, int t, int seg)
{
    const int jloc = t & 127;
    const int quarter = t >> 7;
    const float* xs = (const float*)(sm + OFF_CX);
    const float* ys = (const float*)(sm + OFF_CY);
    const float* kz = (const float*)(sm + OFF_CZ);
    const int j = seg * 128 + jloc;
    const float jx = xs[j], jy = ys[j], Krj = kz[j];
    const float Km2jx = -2.0f * KC * jx;
    const float Km2jy = -2.0f * KC * jy;

    const u64 Kx2 = pk2f(Km2jx, Km2jx);
    const u64 Ky2 = pk2f(Km2jy, Km2jy);
    const u64 Kr2 = pk2f(Krj, Krj);

    const ulonglong2* X2 = (const ulonglong2*)(xs) + quarter * 64;
    const ulonglong2* Y2 = (const ulonglong2*)(ys) + quarter * 64;
    const ulonglong2* Z2 = (const ulonglong2*)(kz) + quarter * 64;

    u64 S1A = 0ULL, S2A = 0ULL, S1B = 0ULL, S2B = 0ULL;
    #pragma unroll 4
    for (int q = 0; q < 64; q++) {          // 4 points per iteration
        ulonglong2 X = X2[q];
        ulonglong2 Y = Y2[q];
        ulonglong2 Z = Z2[q];

        u64 u0; ADD2(u0, Z.x, Kr2);
        FMA2IO(u0, Y.x, Ky2);
        FMA2IO(u0, X.x, Kx2);
        float ua, ub; up2f(u0, ua, ub);
        u64 e0 = pk2f(fast_exp2(ua), fast_exp2(ub));
        ADD2ACC(S1A, e0);
        u64 p0 = u0; FMA2IO(S2A, p0, e0);

        u64 u1; ADD2(u1, Z.y, Kr2);
        FMA2IO(u1, Y.y, Ky2);
        FMA2IO(u1, X.y, Kx2);
        float uc, ud; up2f(u1, uc, ud);
        u64 e1 = pk2f(fast_exp2(uc), fast_exp2(ud));
        ADD2ACC(S1B, e1);
        u64 p1 = u1; FMA2IO(S2B, p1, e1);
    }

    float a, b, c, d;
    up2f(S1A, a, b); up2f(S1B, c, d);
    float s1 = (a + b) + (c + d);
    up2f(S2A, a, b); up2f(S2B, c, d);
    float s2 = (a + b) + (c + d);
    redw[quarter * 128 + jloc] = s1;
    redd[quarter * 128 + jloc] = s2 * INV_KC;
}

// ---------------------------------------------------------------------------
// Fused kernel: per CTA, 128 rows of one batch. grid=256, block=512.
// Even warps: MMA then pairwise.  Odd warps: pairwise then MMA.
// ---------------------------------------------------------------------------
__global__ void __launch_bounds__(512, 1) fused_kernel(
    const float* __restrict__ x,
    const float* __restrict__ mask,
    const float* __restrict__ A,
    const float* __restrict__ bias,
    float* __restrict__ out)
{
    extern __shared__ __align__(1024) char sm[];
    const u32 sbase = smem_u32(sm);
    const int t = threadIdx.x;
    const int wid = t >> 5;
    const int lane = t & 31;

    const int b   = blockIdx.x >> 3;
    const int seg = blockIdx.x & 7;
    const int row0 = b * NN + seg * 128;

    float* xs = (float*)(sm + OFF_CX);
    float* ys = (float*)(sm + OFF_CY);
    float* kz = (float*)(sm + OFF_CZ);
    float* c1s = (float*)(sm + OFF_COEF);
    float* c2s = c1s + 128;
    float* ms  = c2s + 128;
    float* redw = (float*)(sm + OFF_RED);
    float* redd = redw + 512;
    float* A2s = (float*)(sm + OFF_A2);
    float* bs  = (float*)(sm + OFF_BS);

    // ---- prologue loads ----
    // coords SoA for whole batch
    for (int i = t; i < NN; i += 512) {
        float2 c = *(const float2*)(x + ((size_t)b * NN + i) * NF + (NF - 2));
        float r = fmaf(c.y, c.y, c.x * c.x);
        xs[i] = c.x;
        ys[i] = c.y;
        kz[i] = KC * r;
    }

    // x tile -> bf16 hi/lo into padded smem. thread: row=t>>2, 16 cols
    {
        int row = t >> 2;
        int cb  = (t & 3) * 16;
        const float* xr = x + (size_t)(row0 + row) * NF + cb;
        char* xh = sm + OFF_XHI + row * 144 + cb * 2;
        char* xl = sm + OFF_XLO + row * 144 + cb * 2;
        #pragma unroll
        for (int q = 0; q < 4; q++) {
            float4 v = *(const float4*)(xr + q * 4);
            __nv_bfloat16 h0 = __float2bfloat16_rn(v.x);
            __nv_bfloat16 h1 = __float2bfloat16_rn(v.y);
            __nv_bfloat16 h2 = __float2bfloat16_rn(v.z);
            __nv_bfloat16 h3 = __float2bfloat16_rn(v.w);
            __nv_bfloat16 l0 = __float2bfloat16_rn(v.x - __bfloat162float(h0));
            __nv_bfloat16 l1 = __float2bfloat16_rn(v.y - __bfloat162float(h1));
            __nv_bfloat16 l2 = __float2bfloat16_rn(v.z - __bfloat162float(h2));
            __nv_bfloat16 l3 = __float2bfloat16_rn(v.w - __bfloat162float(h3));
            u32 hi01 = ((u32)__bfloat16_as_ushort(h1) << 16) | __bfloat16_as_ushort(h0);
            u32 hi23 = ((u32)__bfloat16_as_ushort(h3) << 16) | __bfloat16_as_ushort(h2);
            u32 lo01 = ((u32)__bfloat16_as_ushort(l1) << 16) | __bfloat16_as_ushort(l0);
            u32 lo23 = ((u32)__bfloat16_as_ushort(l3) << 16) | __bfloat16_as_ushort(l2);
            *(u32*)(xh + q * 8)     = hi01;
            *(u32*)(xh + q * 8 + 4) = hi23;
            *(u32*)(xl + q * 8)     = lo01;
            *(u32*)(xl + q * 8 + 4) = lo23;
        }
    }

    // B tiles: bf16 globals -> padded smem rows
    {
        const uint4* bh = (const uint4*)Bhi_g;
        const uint4* bl = (const uint4*)Blo_g;
        for (int idx = t; idx < 2048; idx += 512) {        // 256 rows x 8 chunks
            int row = idx >> 3, q = idx & 7;
            char* dst_off = sm + row * 144 + q * 16;
            *(uint4*)(dst_off + OFF_BHI) = bh[idx];
            *(uint4*)(dst_off + OFF_BLO) = bl[idx];
        }
    }

    if (t < 128) {
        A2s[t] = A[128 * 128 + t];
        bs[t]  = bias[t];
    }
    __syncthreads();

    // ---- two phases, order-swapped per warp parity (pipe overlap) ----
    const int m0  = (wid & 3) * 32;     // warp rows
    const int c0w = (wid >> 2) * 32;    // warp G0 col base (G1 = +128)
    const int g = lane >> 3, ri = lane & 7;
    const u32 arow = ri + ((g & 1) << 3);
    const u32 acol = (g >> 1) << 4;
    const u32 brow = ri + ((g >> 1) << 3);
    const u32 bcol = (g & 1) << 4;
    const u32 nbase[4] = { (u32)c0w, (u32)c0w + 16, (u32)c0w + 128, (u32)c0w + 144 };

    float acc[2][8][4];

    if (wid & 1) {
        pair_phase(sm, redw, redd, t, seg);
        mma_phase(acc, sbase, m0, nbase, arow, acol, brow, bcol);
    } else {
        mma_phase(acc, sbase, m0, nbase, arow, acol, brow, bcol);
        pair_phase(sm, redw, redd, t, seg);
    }
    __syncthreads();

    if (t < 128) {
        float ws = (redw[t] + redw[128 + t]) + (redw[256 + t] + redw[384 + t]);
        float dw = (redd[t] + redd[128 + t]) + (redd[256 + t] + redd[384 + t]);
        float m = mask[row0 + t];
        ms[t]  = m;
        c1s[t] = fmaf(ws, m, -1.0f);
        c2s[t] = dw * m;
    }
    __syncthreads();

    // ---- epilogue ----
    #pragma unroll
    for (int mt = 0; mt < 2; mt++) {
        const int r1 = m0 + mt * 16 + (lane >> 2);
        const int r2 = r1 + 8;
        const float m1 = ms[r1],  mA = ms[r2];
        const float c11 = c1s[r1], c12 = c1s[r2];
        const float c21 = c2s[r1], c22 = c2s[r2];
        #pragma unroll
        for (int nb = 0; nb < 4; nb++) {
            const int col = c0w + nb * 8 + (lane & 3) * 2;
            const float a20 = A2s[col], a21 = A2s[col + 1];
            const float b0 = bs[col],  b1 = bs[col + 1];
            const float* g0 = acc[mt][nb];
            const float* g1 = acc[mt][nb + 4];
            float2 o1, o2;
            o1.x = (fmaf(c11, g1[0], g0[0]) + fmaf(c21, a20, b0)) * m1;
            o1.y = (fmaf(c11, g1[1], g0[1]) + fmaf(c21, a21, b1)) * m1;
            o2.x = (fmaf(c12, g1[2], g0[2]) + fmaf(c22, a20, b0)) * mA;
            o2.y = (fmaf(c12, g1[3], g0[3]) + fmaf(c22, a21, b1)) * mA;
            *(float2*)(out + (size_t)(row0 + r1) * NO + col) = o1;
            *(float2*)(out + (size_t)(row0 + r2) * NO + col) = o2;
        }
    }
}

extern "C" void kernel_launch(void* const* d_in, const int* in_sizes, int n_in,
                              void* d_out, int out_size) {
    const float* x    = (const float*)d_in[0];
    const float* mask = (const float*)d_in[1];
    const float* A    = (const float*)d_in[2];
    const float* bias = (const float*)d_in[3];
    float* out = (float*)d_out;

    cudaFuncSetAttribute(fused_kernel, cudaFuncAttributeMaxDynamicSharedMemorySize, SMEM_TOTAL);

    prep_kernel<<<16, 1024>>>(A);
    fused_kernel<<<NB * 8, 512, SMEM_TOTAL>>>(x, mask, A, bias, out);
}